// round 14
// baseline (speedup 1.0000x reference)
#include <cuda_runtime.h>
#include <cuda_bf16.h>
#include <math.h>
#include <stdint.h>

#define NB     2048
#define NDIM   512
#define NTOK   64
#define NCODE  1024
#define NA     16384
#define KSPLIT 1536            // MLP2 input: [h2h|h2l|h2h]
#define KH1    3072            // MLP1 input: [hh|hl|hh]
#define KCNT   2048            // count GEMM K: [cnt|cnt] . [wh|wl]
#define CAP    64              // per-row candidate cap

// ---------------- scratch (device globals) ----------------------------------
__device__ float g_cnorm[NA];
__device__ int   g_maxcn_i = 0;
__device__ unsigned long long g_minkey[NB];
__device__ int   g_ccnt[NB];
__device__ int   g_cand[NB * CAP];
__device__ float g_esumsq[NB];
__device__ float g_e    [(size_t)NB * NDIM];
__device__ __nv_bfloat16 g_cntA[(size_t)(2 * NB) * KCNT];  // 16 MB count rows
__device__ __nv_bfloat16 g_ews [(size_t)512 * KCNT];       //  2 MB table split
__device__ __nv_bfloat16 g_hA  [(size_t)NB * KH1];
__device__ __nv_bfloat16 g_h2A [(size_t)NB * KSPLIT];
__device__ __nv_bfloat16 g_Aeh [(size_t)NB * NDIM];
__device__ __nv_bfloat16 g_Bch [(size_t)NA * NDIM];
__device__ __nv_bfloat16 g_w1s [(size_t)512 * KH1];
__device__ __nv_bfloat16 g_w2s [(size_t)512 * KSPLIT];

// ---------------- helpers ----------------------------------------------------
__device__ __forceinline__ uint32_t smem_u32(const void* p) {
    uint32_t a;
    asm("{ .reg .u64 t; cvta.to.shared.u64 t, %1; cvt.u32.u64 %0, t; }" : "=r"(a) : "l"(p));
    return a;
}
__device__ __forceinline__ unsigned int fkey(float f) {
    unsigned int u = __float_as_uint(f);
    return (u & 0x80000000u) ? ~u : (u | 0x80000000u);
}
__device__ __forceinline__ float funkey(uint32_t k) {
    return (k & 0x80000000u) ? __uint_as_float(k & 0x7FFFFFFFu) : __uint_as_float(~k);
}
#define SW128(x) ((x) ^ (((x) >> 3) & 0x70))

#define LDSM_X4(r0, r1, r2, r3, a)                                              \
    asm volatile("ldmatrix.sync.aligned.m8n8.x4.shared.b16 {%0,%1,%2,%3}, [%4];" \
                 : "=r"(r0), "=r"(r1), "=r"(r2), "=r"(r3) : "r"(a) : "memory")

#define MMA16816(d, a, b)                                                       \
    asm volatile("mma.sync.aligned.m16n8k16.row.col.f32.bf16.bf16.f32 "         \
                 "{%0,%1,%2,%3},{%4,%5,%6,%7},{%8,%9},{%0,%1,%2,%3};"           \
                 : "+f"((d)[0]), "+f"((d)[1]), "+f"((d)[2]), "+f"((d)[3])       \
                 : "r"((a)[0]), "r"((a)[1]), "r"((a)[2]), "r"((a)[3]),          \
                   "r"((b)[0]), "r"((b)[1]))

#define CP16(dst, src) asm volatile("cp.async.cg.shared.global [%0], [%1], 16;" \
                                    :: "r"(dst), "l"(src) : "memory")
#define CPCOMMIT()     asm volatile("cp.async.commit_group;" ::: "memory")
#define CPWAIT(n)      asm volatile("cp.async.wait_group %0;" :: "n"(n) : "memory")

// ---------------- fused prep: cb + w1 + w2 + ew splits + init ------------------
__global__ void k_prep(const float* __restrict__ cb, const float* __restrict__ w1,
                       const float* __restrict__ w2, const float* __restrict__ ew) {
    int bb = blockIdx.x, t = threadIdx.x;
    if (bb < NA) {
        __shared__ float red[16];
        float v = cb[(size_t)bb * NDIM + t];
        g_Bch[(size_t)bb * NDIM + t] = __float2bfloat16(v);
        float s = v * v;
        #pragma unroll
        for (int o = 16; o; o >>= 1) s += __shfl_down_sync(0xFFFFFFFFu, s, o);
        if ((t & 31) == 0) red[t >> 5] = s;
        __syncthreads();
        if (t < 16) {
            s = red[t];
            #pragma unroll
            for (int o = 8; o; o >>= 1) s += __shfl_down_sync(0xFFFFu, s, o);
            if (t == 0) {
                g_cnorm[bb] = s;
                atomicMax(&g_maxcn_i, __float_as_int(s));
            }
        }
    } else if (bb < NA + 512) {                       // w1 transpose+split
        int n = bb - NA;
        const int K = 1024;
        for (int k = t; k < K; k += 512) {
            float v = w1[(size_t)k * 512 + n];
            __nv_bfloat16 h = __float2bfloat16(v);
            __nv_bfloat16 l = __float2bfloat16(v - __bfloat162float(h));
            size_t base = (size_t)n * KH1;
            g_w1s[base + k]         = h;
            g_w1s[base + K + k]     = h;
            g_w1s[base + 2 * K + k] = l;
        }
    } else if (bb < NA + 1024) {                      // w2 transpose+split
        int n = bb - NA - 512;
        const int K = 512;
        for (int k = t; k < K; k += 512) {
            float v = w2[(size_t)k * 512 + n];
            __nv_bfloat16 h = __float2bfloat16(v);
            __nv_bfloat16 l = __float2bfloat16(v - __bfloat162float(h));
            size_t base = (size_t)n * KSPLIT;
            g_w2s[base + k]         = h;
            g_w2s[base + K + k]     = h;
            g_w2s[base + 2 * K + k] = l;
        }
    } else if (bb < NA + 1536) {                      // embed table transpose+split [wh|wl]
        int n = bb - NA - 1024;
        for (int k = t; k < NCODE; k += 512) {
            float v = ew[(size_t)k * NDIM + n];
            __nv_bfloat16 h = __float2bfloat16(v);
            __nv_bfloat16 l = __float2bfloat16(v - __bfloat162float(h));
            size_t base = (size_t)n * KCNT;
            g_ews[base + k]         = h;
            g_ews[base + NCODE + k] = l;
        }
    } else {                                          // per-run init
        int i = (bb - NA - 1536) * 512 + t;
        if (i < NB) {
            g_minkey[i] = 0xFFFFFFFFFFFFFFFFull;
            g_ccnt[i] = 0;
            g_esumsq[i] = 0.f;
        }
    }
}

// ---------------- count matrix: Cnt[b*2+half, 2048] = [cnt|cnt] bf16 ----------
__global__ __launch_bounds__(128) void k_cnt(const int* __restrict__ zt,
                                             const int* __restrict__ zp) {
    __shared__ int cnt[2 * NCODE];
    int b = blockIdx.x, t = threadIdx.x;
    for (int i = t; i < 2 * NCODE; i += 128) cnt[i] = 0;
    __syncthreads();
    if (t < NTOK) {
        int c = zt[(size_t)b * NTOK + t];
        c = (c < 0) ? 0 : ((c >= NCODE) ? NCODE - 1 : c);
        atomicAdd(&cnt[c], 1);
    } else {
        int c = zp[(size_t)b * NTOK + (t - NTOK)];
        c = (c < 0) ? 0 : ((c >= NCODE) ? NCODE - 1 : c);
        atomicAdd(&cnt[NCODE + c], 1);
    }
    __syncthreads();
    size_t r0 = (size_t)(b * 2) * KCNT;
    size_t r1 = (size_t)(b * 2 + 1) * KCNT;
    for (int i = t; i < NCODE; i += 128) {
        __nv_bfloat16 c0 = __float2bfloat16((float)cnt[i]);
        __nv_bfloat16 c1 = __float2bfloat16((float)cnt[NCODE + i]);
        g_cntA[r0 + i]         = c0;
        g_cntA[r0 + NCODE + i] = c0;
        g_cntA[r1 + i]         = c1;
        g_cntA[r1 + NCODE + i] = c1;
    }
}

// ---------------- GEMM on mma.sync: tile 64x128, 8 warps, 3-stage -------------
// MODE 0: +bias, gelu, 3-seg split -> outS (stride KSPLIT)      [MLP1]
// MODE 1: +bias, -> g_e fp32 + g_Aeh bf16 + g_esumsq            [MLP2]
// MODE 2: *1/64, -> g_hA 3-seg split (row = b*2+half)           [embed]
#define MLP_SMEM 74240
template <int MODE>
__global__ __launch_bounds__(256)
void k_mlp(const __nv_bfloat16* __restrict__ Ag, const __nv_bfloat16* __restrict__ Bg,
           const float* __restrict__ bias, __nv_bfloat16* __restrict__ outS, int K) {
    extern __shared__ char smem[];
    uint32_t sb = smem_u32(smem);
    float* bias_s = (float*)(smem + 73728);

    int tid = threadIdx.x;
    int lane = tid & 31, wid = tid >> 5;
    int warp_m = wid & 1, warp_n = wid >> 1;
    int m0 = blockIdx.y * 64, n0 = blockIdx.x * 128;
    int nch = K / 64;

    if (MODE != 2 && tid < 128) bias_s[tid] = bias[n0 + tid];

    int j = lane >> 3, lr = lane & 7;
    int arow = warp_m * 32 + ((j & 1) << 3) + lr;
    int ar7 = arow & 7, ajhi = j >> 1;
    int brow = warp_n * 32 + ((j >> 1) << 3) + lr;
    int br7 = brow & 7, bjlo = j & 1;

    float acc[2][4][4];
    #pragma unroll
    for (int mi = 0; mi < 2; mi++)
        #pragma unroll
        for (int nj = 0; nj < 4; nj++)
            #pragma unroll
            for (int q = 0; q < 4; q++) acc[mi][nj][q] = 0.f;

    auto load = [&](int buf, int c) {
        uint32_t ab = sb + (uint32_t)buf * 24576u;
        uint32_t bb2 = ab + 8192u;
        #pragma unroll
        for (int i = 0; i < 2; i++) {
            int u = tid + i * 256;
            int r = u >> 3, g = u & 7;
            uint32_t off = SW128((uint32_t)(r * 128 + g * 16));
            CP16(ab + off, Ag + (size_t)(m0 + r) * K + c * 64 + g * 8);
        }
        #pragma unroll
        for (int i = 0; i < 4; i++) {
            int u = tid + i * 256;
            int r = u >> 3, g = u & 7;
            uint32_t off = SW128((uint32_t)(r * 128 + g * 16));
            CP16(bb2 + off, Bg + (size_t)(n0 + r) * K + c * 64 + g * 8);
        }
    };

    load(0, 0); CPCOMMIT();
    load(1, 1); CPCOMMIT();

    for (int c = 0; c < nch; c++) {
        if (c + 2 < nch) { load((c + 2) % 3, c + 2); CPCOMMIT(); CPWAIT(2); }
        else if (c + 1 < nch) CPWAIT(1);
        else CPWAIT(0);
        __syncthreads();
        uint32_t ab = sb + (uint32_t)(c % 3) * 24576u;
        uint32_t bb2 = ab + 8192u;
        #pragma unroll
        for (int s = 0; s < 4; s++) {
            uint32_t af[2][4];
            uint32_t aaddr = ab + (uint32_t)(arow * 128 + (((2 * s + ajhi) ^ ar7) << 4));
            LDSM_X4(af[0][0], af[0][1], af[0][2], af[0][3], aaddr);
            LDSM_X4(af[1][0], af[1][1], af[1][2], af[1][3], aaddr + 2048u);
            uint32_t bf[8];
            uint32_t baddr = bb2 + (uint32_t)(brow * 128 + (((2 * s + bjlo) ^ br7) << 4));
            #pragma unroll
            for (int p = 0; p < 2; p++)
                LDSM_X4(bf[4 * p], bf[4 * p + 1], bf[4 * p + 2], bf[4 * p + 3],
                        baddr + (uint32_t)(p * 2048));
            #pragma unroll
            for (int mi = 0; mi < 2; mi++)
                #pragma unroll
                for (int nj = 0; nj < 4; nj++) {
                    uint32_t b2[2] = {bf[(nj >> 1) * 4 + (nj & 1) * 2],
                                      bf[(nj >> 1) * 4 + (nj & 1) * 2 + 1]};
                    MMA16816(acc[mi][nj], af[mi], b2);
                }
        }
        __syncthreads();
    }

    int qr = lane >> 2, qc = lane & 3;
    #pragma unroll
    for (int mi = 0; mi < 2; mi++) {
        #pragma unroll
        for (int h = 0; h < 2; h++) {
            int row = m0 + warp_m * 32 + mi * 16 + h * 8 + qr;
            float sq = 0.f;
            #pragma unroll
            for (int nj = 0; nj < 4; nj++) {
                int lc = warp_n * 32 + nj * 8 + qc * 2;
                int gc = n0 + lc;
                float v0, v1;
                if (MODE == 2) {
                    v0 = acc[mi][nj][h * 2 + 0] * (1.f / 64.f);
                    v1 = acc[mi][nj][h * 2 + 1] * (1.f / 64.f);
                } else {
                    v0 = acc[mi][nj][h * 2 + 0] + bias_s[lc];
                    v1 = acc[mi][nj][h * 2 + 1] + bias_s[lc + 1];
                }
                if (MODE == 0) { v0 = v0 * normcdff(v0); v1 = v1 * normcdff(v1); }
                __nv_bfloat16 h0 = __float2bfloat16(v0);
                __nv_bfloat16 h1 = __float2bfloat16(v1);
                __nv_bfloat162 ph; ph.x = h0; ph.y = h1;
                if (MODE == 0) {
                    __nv_bfloat16 l0 = __float2bfloat16(v0 - __bfloat162float(h0));
                    __nv_bfloat16 l1 = __float2bfloat16(v1 - __bfloat162float(h1));
                    __nv_bfloat162 pl; pl.x = l0; pl.y = l1;
                    __nv_bfloat162* base = (__nv_bfloat162*)(outS + (size_t)row * KSPLIT + gc);
                    base[0] = ph;
                    *(__nv_bfloat162*)((__nv_bfloat16*)base + 512)  = pl;
                    *(__nv_bfloat162*)((__nv_bfloat16*)base + 1024) = ph;
                } else if (MODE == 1) {
                    *(float2*)(g_e + (size_t)row * NDIM + gc) = make_float2(v0, v1);
                    *(__nv_bfloat162*)(g_Aeh + (size_t)row * NDIM + gc) = ph;
                    sq += v0 * v0 + v1 * v1;
                } else {
                    __nv_bfloat16 l0 = __float2bfloat16(v0 - __bfloat162float(h0));
                    __nv_bfloat16 l1 = __float2bfloat16(v1 - __bfloat162float(h1));
                    __nv_bfloat162 pl; pl.x = l0; pl.y = l1;
                    int b = row >> 1, half = row & 1;
                    __nv_bfloat16* base = g_hA + (size_t)b * KH1 + half * 512 + gc;
                    *(__nv_bfloat162*)(base)        = ph;
                    *(__nv_bfloat162*)(base + 1024) = pl;
                    *(__nv_bfloat162*)(base + 2048) = ph;
                }
            }
            if (MODE == 1) {
                sq += __shfl_xor_sync(0xFFFFFFFFu, sq, 1);
                sq += __shfl_xor_sync(0xFFFFFFFFu, sq, 2);
                if (qc == 0) atomicAdd(&g_esumsq[row], sq);
            }
        }
    }
}

// ---------------- VQ phase 1: CTA 128x128, 4 warps, warp 64x64, 3-stage -------
#define VQ_SMEM 100864
#define VQ1_NCH (NDIM / 64)    // 8

__global__ __launch_bounds__(128, 2) void k_vq1() {
    extern __shared__ char smem[];
    uint32_t sb = smem_u32(smem);
    unsigned long long* red = (unsigned long long*)(smem + 98304);
    float* cns  = (float*)(smem + 99328);
    float* tmin = (float*)(smem + 99840);
    float* marg = (float*)(smem + 100352);

    int tid = threadIdx.x;
    int lane = tid & 31, wid = tid >> 5;
    int warp_m = wid & 1, warp_n = wid >> 1;
    int m0 = blockIdx.y * 128, n0 = blockIdx.x * 128;

    red[tid]  = 0xFFFFFFFFFFFFFFFFull;
    marg[tid] = 0.0117f * sqrtf(g_esumsq[m0 + tid] * __int_as_float(g_maxcn_i)) + 1e-5f;
    cns[tid]  = g_cnorm[n0 + tid];

    int j = lane >> 3, lr = lane & 7;
    int arow = warp_m * 64 + ((j & 1) << 3) + lr;
    int ar7 = arow & 7, ajhi = j >> 1;
    int brow = warp_n * 64 + ((j >> 1) << 3) + lr;
    int br7 = brow & 7, bjlo = j & 1;

    float acc[4][8][4];
    #pragma unroll
    for (int mi = 0; mi < 4; mi++)
        #pragma unroll
        for (int nj = 0; nj < 8; nj++)
            #pragma unroll
            for (int q = 0; q < 4; q++) acc[mi][nj][q] = 0.f;

    auto load = [&](int buf, int c) {
        uint32_t ab = sb + (uint32_t)buf * 32768u;
        uint32_t bb2 = ab + 16384u;
        #pragma unroll
        for (int i = 0; i < 8; i++) {
            int u = tid + i * 128;
            int r = u >> 3, g = u & 7;
            uint32_t off = SW128((uint32_t)(r * 128 + g * 16));
            CP16(ab + off,  g_Aeh + (size_t)(m0 + r) * NDIM + c * 64 + g * 8);
            CP16(bb2 + off, g_Bch + (size_t)(n0 + r) * NDIM + c * 64 + g * 8);
        }
    };

    load(0, 0); CPCOMMIT();
    load(1, 1); CPCOMMIT();

    for (int c = 0; c < VQ1_NCH; c++) {
        if (c + 2 < VQ1_NCH) { load((c + 2) % 3, c + 2); CPCOMMIT(); CPWAIT(2); }
        else if (c + 1 < VQ1_NCH) CPWAIT(1);
        else CPWAIT(0);
        __syncthreads();

        uint32_t ab = sb + (uint32_t)(c % 3) * 32768u;
        uint32_t bb2 = ab + 16384u;
        #pragma unroll
        for (int s = 0; s < 4; s++) {
            uint32_t af[4][4];
            uint32_t aaddr = ab + (uint32_t)(arow * 128 + (((2 * s + ajhi) ^ ar7) << 4));
            #pragma unroll
            for (int mi = 0; mi < 4; mi++)
                LDSM_X4(af[mi][0], af[mi][1], af[mi][2], af[mi][3],
                        aaddr + (uint32_t)(mi * 2048));
            uint32_t bf[16];
            uint32_t baddr = bb2 + (uint32_t)(brow * 128 + (((2 * s + bjlo) ^ br7) << 4));
            #pragma unroll
            for (int p = 0; p < 4; p++)
                LDSM_X4(bf[4 * p], bf[4 * p + 1], bf[4 * p + 2], bf[4 * p + 3],
                        baddr + (uint32_t)(p * 2048));
            #pragma unroll
            for (int mi = 0; mi < 4; mi++)
                #pragma unroll
                for (int nj = 0; nj < 8; nj++) {
                    uint32_t b2[2] = {bf[(nj >> 1) * 4 + (nj & 1) * 2],
                                      bf[(nj >> 1) * 4 + (nj & 1) * 2 + 1]};
                    MMA16816(acc[mi][nj], af[mi], b2);
                }
        }
        __syncthreads();
    }

    int qr = lane >> 2, qc = lane & 3;
    #pragma unroll
    for (int mi = 0; mi < 4; mi++) {
        #pragma unroll
        for (int h = 0; h < 2; h++) {
            int rowl = warp_m * 64 + mi * 16 + h * 8 + qr;
            float best = __int_as_float(0x7F800000);
            int bi = 0;
            #pragma unroll
            for (int nj = 0; nj < 8; nj++) {
                int col = warp_n * 64 + nj * 8 + qc * 2;
                float s0 = cns[col]     - 2.0f * acc[mi][nj][h * 2 + 0];
                float s1 = cns[col + 1] - 2.0f * acc[mi][nj][h * 2 + 1];
                if (s0 < best) { best = s0; bi = col; }
                if (s1 < best) { best = s1; bi = col + 1; }
            }
            unsigned long long key =
                ((unsigned long long)fkey(best) << 32) | (unsigned int)(n0 + bi);
            #pragma unroll
            for (int off = 1; off <= 2; off <<= 1) {
                unsigned long long o = __shfl_xor_sync(0xFFFFFFFFu, key, off);
                if (o < key) key = o;
            }
            if (qc == 0) atomicMin(&red[rowl], key);
        }
    }
    __syncthreads();

    {
        unsigned long long mine = red[tid];
        unsigned long long old = atomicMin(&g_minkey[m0 + tid], mine);
        unsigned long long cur = old < mine ? old : mine;
        tmin[tid] = funkey((uint32_t)(cur >> 32)) + marg[tid];
    }
    __syncthreads();

    #pragma unroll
    for (int mi = 0; mi < 4; mi++) {
        #pragma unroll
        for (int h = 0; h < 2; h++) {
            int rowl = warp_m * 64 + mi * 16 + h * 8 + qr;
            int row = m0 + rowl;
            float T = tmin[rowl];
            #pragma unroll
            for (int nj = 0; nj < 8; nj++) {
                int col = warp_n * 64 + nj * 8 + qc * 2;
                float s0 = cns[col]     - 2.0f * acc[mi][nj][h * 2 + 0];
                float s1 = cns[col + 1] - 2.0f * acc[mi][nj][h * 2 + 1];
                if (s0 <= T) {
                    int id = atomicAdd(&g_ccnt[row], 1);
                    if (id < CAP) g_cand[row * CAP + id] = n0 + col;
                }
                if (s1 <= T) {
                    int id = atomicAdd(&g_ccnt[row], 1);
                    if (id < CAP) g_cand[row * CAP + id] = n0 + col + 1;
                }
            }
        }
    }
}

// ---------------- VQ phase 2: exact fp32 rescore of candidates + output -------
__global__ __launch_bounds__(256) void k_refine(const float* __restrict__ cb,
                                                float* __restrict__ out) {
    __shared__ float es[512];
    __shared__ unsigned long long wkey[8];
    __shared__ int bid_s;

    int b = blockIdx.x, t = threadIdx.x;
    int lane = t & 31, w = t >> 5;

    es[t]       = g_e[(size_t)b * NDIM + t];
    es[256 + t] = g_e[(size_t)b * NDIM + 256 + t];
    __syncthreads();

    int nc = g_ccnt[b];
    bool ovf = nc > CAP;
    int total = ovf ? NA : nc;

    unsigned long long best = 0xFFFFFFFFFFFFFFFFull;
    for (int ci = w; ci < total; ci += 8) {
        int code = ovf ? ci : g_cand[b * CAP + ci];
        const float* cr = cb + (size_t)code * NDIM;
        float d = 0.f;
        #pragma unroll
        for (int i = 0; i < 16; i++) d += es[lane + i * 32] * cr[lane + i * 32];
        #pragma unroll
        for (int o = 16; o; o >>= 1) d += __shfl_down_sync(0xFFFFFFFFu, d, o);
        if (lane == 0) {
            float s = g_cnorm[code] - 2.0f * d;
            unsigned long long k =
                ((unsigned long long)fkey(s) << 32) | (unsigned int)code;
            if (k < best) best = k;
        }
    }
    if (lane == 0) wkey[w] = best;
    __syncthreads();
    if (t == 0) {
        unsigned long long k = wkey[0];
        #pragma unroll
        for (int i = 1; i < 8; i++) if (wkey[i] < k) k = wkey[i];
        int bi = (int)(k & 0xFFFFFFFFull);
        if (bi < 0 || bi >= NA) bi = 0;
        out[b] = (float)bi;
        bid_s = bi;
    }
    __syncthreads();
    int bi = bid_s;
    out[NB + (size_t)b * NDIM + t]       = cb[(size_t)bi * NDIM + t];
    out[NB + (size_t)b * NDIM + 256 + t] = cb[(size_t)bi * NDIM + 256 + t];
}

// -------------------------------------------------------------------------------
extern "C" void kernel_launch(void* const* d_in, const int* in_sizes, int n_in,
                              void* d_out, int out_size) {
    const int*   zt = (const int*)d_in[0];
    const int*   zp = (const int*)d_in[1];
    const float* ew = (const float*)d_in[2];
    const float* w1 = (const float*)d_in[3];
    const float* b1 = (const float*)d_in[4];
    const float* w2 = (const float*)d_in[5];
    const float* b2 = (const float*)d_in[6];
    const float* cb = (const float*)d_in[7];
    float* out = (float*)d_out;

    __nv_bfloat16 *phA, *ph2A, *pw1s, *pw2s, *pcnt, *pews;
    cudaGetSymbolAddress((void**)&phA,  g_hA);
    cudaGetSymbolAddress((void**)&ph2A, g_h2A);
    cudaGetSymbolAddress((void**)&pw1s, g_w1s);
    cudaGetSymbolAddress((void**)&pw2s, g_w2s);
    cudaGetSymbolAddress((void**)&pcnt, g_cntA);
    cudaGetSymbolAddress((void**)&pews, g_ews);

    cudaFuncSetAttribute(k_vq1, cudaFuncAttributeMaxDynamicSharedMemorySize, VQ_SMEM);
    cudaFuncSetAttribute((const void*)k_mlp<0>, cudaFuncAttributeMaxDynamicSharedMemorySize, MLP_SMEM);
    cudaFuncSetAttribute((const void*)k_mlp<1>, cudaFuncAttributeMaxDynamicSharedMemorySize, MLP_SMEM);
    cudaFuncSetAttribute((const void*)k_mlp<2>, cudaFuncAttributeMaxDynamicSharedMemorySize, MLP_SMEM);

    k_prep <<<NA + 1536 + (NB + 511) / 512, 512>>>(cb, w1, w2, ew);
    k_cnt  <<<NB, 128>>>(zt, zp);
    // embed GEMM: h[4096, 512] = Cnt[4096, 2048] @ ews^T / 64 -> g_hA split
    k_mlp<2><<<dim3(4, 2 * NB / 64), 256, MLP_SMEM>>>(pcnt, pews, nullptr, nullptr, KCNT);
    k_mlp<0><<<dim3(4, NB / 64), 256, MLP_SMEM>>>(phA,  pw1s, b1, ph2A, KH1);
    k_mlp<1><<<dim3(4, NB / 64), 256, MLP_SMEM>>>(ph2A, pw2s, b2, nullptr, KSPLIT);
    k_vq1  <<<dim3(NA / 128, NB / 128), 128, VQ_SMEM>>>();
    k_refine<<<NB, 256>>>(cb, out);
}

// round 15
// speedup vs baseline: 1.0645x; 1.0645x over previous
#include <cuda_runtime.h>
#include <cuda_bf16.h>
#include <math.h>
#include <stdint.h>

#define NB     2048
#define NDIM   512
#define NTOK   64
#define NCODE  1024
#define NA     16384
#define KSPLIT 1536            // MLP2 input: [h2h|h2l|h2h]
#define KH1    3072            // MLP1 input: [hh|hl|hh]
#define CAP    64              // per-row candidate cap

// ---------------- scratch (device globals) ----------------------------------
__device__ float g_cnorm[NA];
__device__ int   g_maxcn_i = 0;
__device__ unsigned long long g_minkey[NB];
__device__ int   g_ccnt[NB];
__device__ int   g_cand[NB * CAP];
__device__ float g_margin[NB];
__device__ float g_e    [(size_t)NB * NDIM];
__device__ __nv_bfloat16 g_hA  [(size_t)NB * KH1];
__device__ __nv_bfloat16 g_h2A [(size_t)NB * KSPLIT];
__device__ __nv_bfloat16 g_Aeh [(size_t)NB * NDIM];
__device__ __nv_bfloat16 g_Bch [(size_t)NA * NDIM];
__device__ __nv_bfloat16 g_w1s [(size_t)512 * KH1];
__device__ __nv_bfloat16 g_w2s [(size_t)512 * KSPLIT];

// ---------------- helpers ----------------------------------------------------
__device__ __forceinline__ uint32_t smem_u32(const void* p) {
    uint32_t a;
    asm("{ .reg .u64 t; cvta.to.shared.u64 t, %1; cvt.u32.u64 %0, t; }" : "=r"(a) : "l"(p));
    return a;
}
__device__ __forceinline__ unsigned int fkey(float f) {
    unsigned int u = __float_as_uint(f);
    return (u & 0x80000000u) ? ~u : (u | 0x80000000u);
}
__device__ __forceinline__ float funkey(uint32_t k) {
    return (k & 0x80000000u) ? __uint_as_float(k & 0x7FFFFFFFu) : __uint_as_float(~k);
}
#define SW128(x) ((x) ^ (((x) >> 3) & 0x70))

#define LDSM_X4(r0, r1, r2, r3, a)                                              \
    asm volatile("ldmatrix.sync.aligned.m8n8.x4.shared.b16 {%0,%1,%2,%3}, [%4];" \
                 : "=r"(r0), "=r"(r1), "=r"(r2), "=r"(r3) : "r"(a) : "memory")

#define MMA16816(d, a, b)                                                       \
    asm volatile("mma.sync.aligned.m16n8k16.row.col.f32.bf16.bf16.f32 "         \
                 "{%0,%1,%2,%3},{%4,%5,%6,%7},{%8,%9},{%0,%1,%2,%3};"           \
                 : "+f"((d)[0]), "+f"((d)[1]), "+f"((d)[2]), "+f"((d)[3])       \
                 : "r"((a)[0]), "r"((a)[1]), "r"((a)[2]), "r"((a)[3]),          \
                   "r"((b)[0]), "r"((b)[1]))

#define CP16(dst, src) asm volatile("cp.async.cg.shared.global [%0], [%1], 16;" \
                                    :: "r"(dst), "l"(src) : "memory")
#define CPCOMMIT()     asm volatile("cp.async.commit_group;" ::: "memory")
#define CPWAIT(n)      asm volatile("cp.async.wait_group %0;" :: "n"(n) : "memory")

// ---------------- fused prep: cb norms/split + w splits + per-run init --------
__global__ void k_prep(const float* __restrict__ cb, const float* __restrict__ w1,
                       const float* __restrict__ w2) {
    int bb = blockIdx.x, t = threadIdx.x;
    if (bb < NA) {
        __shared__ float red[16];
        float v = cb[(size_t)bb * NDIM + t];
        g_Bch[(size_t)bb * NDIM + t] = __float2bfloat16(v);
        float s = v * v;
        #pragma unroll
        for (int o = 16; o; o >>= 1) s += __shfl_down_sync(0xFFFFFFFFu, s, o);
        if ((t & 31) == 0) red[t >> 5] = s;
        __syncthreads();
        if (t < 16) {
            s = red[t];
            #pragma unroll
            for (int o = 8; o; o >>= 1) s += __shfl_down_sync(0xFFFFu, s, o);
            if (t == 0) {
                g_cnorm[bb] = s;
                atomicMax(&g_maxcn_i, __float_as_int(s));
            }
        }
    } else if (bb < NA + 512) {
        int n = bb - NA;
        const int K = 1024;
        for (int k = t; k < K; k += 512) {
            float v = w1[(size_t)k * 512 + n];
            __nv_bfloat16 h = __float2bfloat16(v);
            __nv_bfloat16 l = __float2bfloat16(v - __bfloat162float(h));
            size_t base = (size_t)n * KH1;
            g_w1s[base + k]         = h;
            g_w1s[base + K + k]     = h;
            g_w1s[base + 2 * K + k] = l;
        }
    } else if (bb < NA + 1024) {
        int n = bb - NA - 512;
        const int K = 512;
        for (int k = t; k < K; k += 512) {
            float v = w2[(size_t)k * 512 + n];
            __nv_bfloat16 h = __float2bfloat16(v);
            __nv_bfloat16 l = __float2bfloat16(v - __bfloat162float(h));
            size_t base = (size_t)n * KSPLIT;
            g_w2s[base + k]         = h;
            g_w2s[base + K + k]     = h;
            g_w2s[base + 2 * K + k] = l;
        }
    } else {
        int i = (bb - NA - 1024) * 512 + t;
        if (i < NB) { g_minkey[i] = 0xFFFFFFFFFFFFFFFFull; g_ccnt[i] = 0; }
    }
}

// ---------------- embedding gather + mean pool -> split h (round-10 exact) ----
__global__ void k_embed(const int* __restrict__ zt, const int* __restrict__ zp,
                        const float* __restrict__ ew) {
    __shared__ int codes[2 * NTOK];
    int b = blockIdx.x, t = threadIdx.x;
    if (t < NTOK) {
        int c = zt[(size_t)b * NTOK + t];
        codes[t] = (c < 0) ? 0 : ((c >= NCODE) ? NCODE - 1 : c);
    } else if (t < 2 * NTOK) {
        int c = zp[(size_t)b * NTOK + (t - NTOK)];
        codes[t] = (c < 0) ? 0 : ((c >= NCODE) ? NCODE - 1 : c);
    }
    __syncthreads();
    float st = 0.f, sp = 0.f;
    #pragma unroll 8
    for (int i = 0; i < NTOK; i++) {
        st += ew[(size_t)codes[i]        * NDIM + t];
        sp += ew[(size_t)codes[NTOK + i] * NDIM + t];
    }
    st *= (1.f / 64.f); sp *= (1.f / 64.f);
    __nv_bfloat16 sh = __float2bfloat16(st);
    __nv_bfloat16 sl = __float2bfloat16(st - __bfloat162float(sh));
    __nv_bfloat16 ph = __float2bfloat16(sp);
    __nv_bfloat16 pl = __float2bfloat16(sp - __bfloat162float(ph));
    size_t base = (size_t)b * KH1;
    g_hA[base + t]        = sh;
    g_hA[base + 512 + t]  = ph;
    g_hA[base + 1024 + t] = sl;
    g_hA[base + 1536 + t] = pl;
    g_hA[base + 2048 + t] = sh;
    g_hA[base + 2560 + t] = ph;
}

// ---------------- MLP GEMM: tile 64x64, 4 warps (2m x 2n), 3-stage pipeline ---
// dyn smem: [A(8K) B(8K)] x3 @ k*16384, bias @49152 (64 f32) -> 49408
#define MLP_SMEM 49408
template <bool GELU, bool SPLIT3>
__global__ __launch_bounds__(128, 3)
void k_mlp(const __nv_bfloat16* __restrict__ Ag, const __nv_bfloat16* __restrict__ Bg,
           const float* __restrict__ bias, __nv_bfloat16* __restrict__ outS, int K) {
    extern __shared__ char smem[];
    uint32_t sb = smem_u32(smem);
    float* bias_s = (float*)(smem + 49152);

    int tid = threadIdx.x;
    int lane = tid & 31, wid = tid >> 5;
    int warp_m = wid & 1, warp_n = wid >> 1;          // 2m x 2n, warp tile 32x32
    int m0 = blockIdx.y * 64, n0 = blockIdx.x * 64;
    int nch = K / 64;

    if (tid < 64) bias_s[tid] = bias[n0 + tid];

    int j = lane >> 3, lr = lane & 7;
    int arow = warp_m * 32 + ((j & 1) << 3) + lr;
    int ar7 = arow & 7, ajhi = j >> 1;
    int brow = warp_n * 32 + ((j >> 1) << 3) + lr;
    int br7 = brow & 7, bjlo = j & 1;

    float acc[2][4][4];
    #pragma unroll
    for (int mi = 0; mi < 2; mi++)
        #pragma unroll
        for (int nj = 0; nj < 4; nj++)
            #pragma unroll
            for (int q = 0; q < 4; q++) acc[mi][nj][q] = 0.f;

    // chunk loader: A 64 rows + B 64 rows, 128 threads -> 4 iters each
    auto load = [&](int buf, int c) {
        uint32_t ab = sb + (uint32_t)buf * 16384u;
        uint32_t bb2 = ab + 8192u;
        #pragma unroll
        for (int i = 0; i < 4; i++) {
            int u = tid + i * 128;
            int r = u >> 3, g = u & 7;
            uint32_t off = SW128((uint32_t)(r * 128 + g * 16));
            CP16(ab + off,  Ag + (size_t)(m0 + r) * K + c * 64 + g * 8);
            CP16(bb2 + off, Bg + (size_t)(n0 + r) * K + c * 64 + g * 8);
        }
    };

    load(0, 0); CPCOMMIT();
    load(1, 1); CPCOMMIT();

    for (int c = 0; c < nch; c++) {
        if (c + 2 < nch) { load((c + 2) % 3, c + 2); CPCOMMIT(); CPWAIT(2); }
        else if (c + 1 < nch) CPWAIT(1);
        else CPWAIT(0);
        __syncthreads();
        uint32_t ab = sb + (uint32_t)(c % 3) * 16384u;
        uint32_t bb2 = ab + 8192u;
        #pragma unroll
        for (int s = 0; s < 4; s++) {
            uint32_t af[2][4];
            uint32_t aaddr = ab + (uint32_t)(arow * 128 + (((2 * s + ajhi) ^ ar7) << 4));
            LDSM_X4(af[0][0], af[0][1], af[0][2], af[0][3], aaddr);
            LDSM_X4(af[1][0], af[1][1], af[1][2], af[1][3], aaddr + 2048u);
            uint32_t bf[8];
            uint32_t baddr = bb2 + (uint32_t)(brow * 128 + (((2 * s + bjlo) ^ br7) << 4));
            #pragma unroll
            for (int p = 0; p < 2; p++)
                LDSM_X4(bf[4 * p], bf[4 * p + 1], bf[4 * p + 2], bf[4 * p + 3],
                        baddr + (uint32_t)(p * 2048));
            #pragma unroll
            for (int mi = 0; mi < 2; mi++)
                #pragma unroll
                for (int nj = 0; nj < 4; nj++) {
                    uint32_t b2[2] = {bf[(nj >> 1) * 4 + (nj & 1) * 2],
                                      bf[(nj >> 1) * 4 + (nj & 1) * 2 + 1]};
                    MMA16816(acc[mi][nj], af[mi], b2);
                }
        }
        __syncthreads();
    }

    int qr = lane >> 2, qc = lane & 3;
    #pragma unroll
    for (int mi = 0; mi < 2; mi++) {
        #pragma unroll
        for (int h = 0; h < 2; h++) {
            int row = m0 + warp_m * 32 + mi * 16 + h * 8 + qr;
            #pragma unroll
            for (int nj = 0; nj < 4; nj++) {
                int lc = warp_n * 32 + nj * 8 + qc * 2;
                float v0 = acc[mi][nj][h * 2 + 0] + bias_s[lc];
                float v1 = acc[mi][nj][h * 2 + 1] + bias_s[lc + 1];
                if (GELU) { v0 = v0 * normcdff(v0); v1 = v1 * normcdff(v1); }
                int gc = n0 + lc;
                if (SPLIT3) {
                    __nv_bfloat16 h0 = __float2bfloat16(v0);
                    __nv_bfloat16 h1 = __float2bfloat16(v1);
                    __nv_bfloat16 l0 = __float2bfloat16(v0 - __bfloat162float(h0));
                    __nv_bfloat16 l1 = __float2bfloat16(v1 - __bfloat162float(h1));
                    __nv_bfloat162 ph; ph.x = h0; ph.y = h1;
                    __nv_bfloat162 pl; pl.x = l0; pl.y = l1;
                    __nv_bfloat162* base = (__nv_bfloat162*)(outS + (size_t)row * KSPLIT + gc);
                    base[0] = ph;
                    *(__nv_bfloat162*)((__nv_bfloat16*)base + 512)  = pl;
                    *(__nv_bfloat162*)((__nv_bfloat16*)base + 1024) = ph;
                } else {
                    *(float2*)(g_e + (size_t)row * NDIM + gc) = make_float2(v0, v1);
                    __nv_bfloat162 ph;
                    ph.x = __float2bfloat16(v0);
                    ph.y = __float2bfloat16(v1);
                    *(__nv_bfloat162*)(g_Aeh + (size_t)row * NDIM + gc) = ph;
                }
            }
        }
    }
}

// per-row margin (round-10 exact)
__global__ void k_emargin() {
    int row = blockIdx.x * 8 + (threadIdx.x >> 5);
    int lane = threadIdx.x & 31;
    const float* e = g_e + (size_t)row * NDIM;
    float s = 0.f;
    #pragma unroll
    for (int i = 0; i < 16; i++) { float v = e[lane + i * 32]; s += v * v; }
    #pragma unroll
    for (int o = 16; o; o >>= 1) s += __shfl_down_sync(0xFFFFFFFFu, s, o);
    if (lane == 0)
        g_margin[row] = 0.0117f * sqrtf(s * __int_as_float(g_maxcn_i)) + 1e-5f;
}

// ---------------- VQ phase 1 (round-10 exact): CTA 128x128, 4 warps, 64x64 ----
#define VQ_SMEM 100864
#define VQ1_NCH (NDIM / 64)    // 8

__global__ __launch_bounds__(128, 2) void k_vq1() {
    extern __shared__ char smem[];
    uint32_t sb = smem_u32(smem);
    unsigned long long* red = (unsigned long long*)(smem + 98304);
    float* cns  = (float*)(smem + 99328);
    float* tmin = (float*)(smem + 99840);
    float* marg = (float*)(smem + 100352);

    int tid = threadIdx.x;
    int lane = tid & 31, wid = tid >> 5;
    int warp_m = wid & 1, warp_n = wid >> 1;
    int m0 = blockIdx.y * 128, n0 = blockIdx.x * 128;

    red[tid]  = 0xFFFFFFFFFFFFFFFFull;
    marg[tid] = g_margin[m0 + tid];
    cns[tid]  = g_cnorm[n0 + tid];

    int j = lane >> 3, lr = lane & 7;
    int arow = warp_m * 64 + ((j & 1) << 3) + lr;
    int ar7 = arow & 7, ajhi = j >> 1;
    int brow = warp_n * 64 + ((j >> 1) << 3) + lr;
    int br7 = brow & 7, bjlo = j & 1;

    float acc[4][8][4];
    #pragma unroll
    for (int mi = 0; mi < 4; mi++)
        #pragma unroll
        for (int nj = 0; nj < 8; nj++)
            #pragma unroll
            for (int q = 0; q < 4; q++) acc[mi][nj][q] = 0.f;

    auto load = [&](int buf, int c) {
        uint32_t ab = sb + (uint32_t)buf * 32768u;
        uint32_t bb2 = ab + 16384u;
        #pragma unroll
        for (int i = 0; i < 8; i++) {
            int u = tid + i * 128;
            int r = u >> 3, g = u & 7;
            uint32_t off = SW128((uint32_t)(r * 128 + g * 16));
            CP16(ab + off,  g_Aeh + (size_t)(m0 + r) * NDIM + c * 64 + g * 8);
            CP16(bb2 + off, g_Bch + (size_t)(n0 + r) * NDIM + c * 64 + g * 8);
        }
    };

    load(0, 0); CPCOMMIT();
    load(1, 1); CPCOMMIT();

    for (int c = 0; c < VQ1_NCH; c++) {
        if (c + 2 < VQ1_NCH) { load((c + 2) % 3, c + 2); CPCOMMIT(); CPWAIT(2); }
        else if (c + 1 < VQ1_NCH) CPWAIT(1);
        else CPWAIT(0);
        __syncthreads();

        uint32_t ab = sb + (uint32_t)(c % 3) * 32768u;
        uint32_t bb2 = ab + 16384u;
        #pragma unroll
        for (int s = 0; s < 4; s++) {
            uint32_t af[4][4];
            uint32_t aaddr = ab + (uint32_t)(arow * 128 + (((2 * s + ajhi) ^ ar7) << 4));
            #pragma unroll
            for (int mi = 0; mi < 4; mi++)
                LDSM_X4(af[mi][0], af[mi][1], af[mi][2], af[mi][3],
                        aaddr + (uint32_t)(mi * 2048));
            uint32_t bf[16];
            uint32_t baddr = bb2 + (uint32_t)(brow * 128 + (((2 * s + bjlo) ^ br7) << 4));
            #pragma unroll
            for (int p = 0; p < 4; p++)
                LDSM_X4(bf[4 * p], bf[4 * p + 1], bf[4 * p + 2], bf[4 * p + 3],
                        baddr + (uint32_t)(p * 2048));
            #pragma unroll
            for (int mi = 0; mi < 4; mi++)
                #pragma unroll
                for (int nj = 0; nj < 8; nj++) {
                    uint32_t b2[2] = {bf[(nj >> 1) * 4 + (nj & 1) * 2],
                                      bf[(nj >> 1) * 4 + (nj & 1) * 2 + 1]};
                    MMA16816(acc[mi][nj], af[mi], b2);
                }
        }
        __syncthreads();
    }

    int qr = lane >> 2, qc = lane & 3;
    #pragma unroll
    for (int mi = 0; mi < 4; mi++) {
        #pragma unroll
        for (int h = 0; h < 2; h++) {
            int rowl = warp_m * 64 + mi * 16 + h * 8 + qr;
            float best = __int_as_float(0x7F800000);
            int bi = 0;
            #pragma unroll
            for (int nj = 0; nj < 8; nj++) {
                int col = warp_n * 64 + nj * 8 + qc * 2;
                float s0 = cns[col]     - 2.0f * acc[mi][nj][h * 2 + 0];
                float s1 = cns[col + 1] - 2.0f * acc[mi][nj][h * 2 + 1];
                if (s0 < best) { best = s0; bi = col; }
                if (s1 < best) { best = s1; bi = col + 1; }
            }
            unsigned long long key =
                ((unsigned long long)fkey(best) << 32) | (unsigned int)(n0 + bi);
            #pragma unroll
            for (int off = 1; off <= 2; off <<= 1) {
                unsigned long long o = __shfl_xor_sync(0xFFFFFFFFu, key, off);
                if (o < key) key = o;
            }
            if (qc == 0) atomicMin(&red[rowl], key);
        }
    }
    __syncthreads();

    {
        unsigned long long mine = red[tid];
        unsigned long long old = atomicMin(&g_minkey[m0 + tid], mine);
        unsigned long long cur = old < mine ? old : mine;
        tmin[tid] = funkey((uint32_t)(cur >> 32)) + marg[tid];
    }
    __syncthreads();

    #pragma unroll
    for (int mi = 0; mi < 4; mi++) {
        #pragma unroll
        for (int h = 0; h < 2; h++) {
            int rowl = warp_m * 64 + mi * 16 + h * 8 + qr;
            int row = m0 + rowl;
            float T = tmin[rowl];
            #pragma unroll
            for (int nj = 0; nj < 8; nj++) {
                int col = warp_n * 64 + nj * 8 + qc * 2;
                float s0 = cns[col]     - 2.0f * acc[mi][nj][h * 2 + 0];
                float s1 = cns[col + 1] - 2.0f * acc[mi][nj][h * 2 + 1];
                if (s0 <= T) {
                    int id = atomicAdd(&g_ccnt[row], 1);
                    if (id < CAP) g_cand[row * CAP + id] = n0 + col;
                }
                if (s1 <= T) {
                    int id = atomicAdd(&g_ccnt[row], 1);
                    if (id < CAP) g_cand[row * CAP + id] = n0 + col + 1;
                }
            }
        }
    }
}

// ---------------- VQ phase 2 (round-10 exact) ----------------------------------
__global__ __launch_bounds__(256) void k_refine(const float* __restrict__ cb,
                                                float* __restrict__ out) {
    __shared__ float es[512];
    __shared__ unsigned long long wkey[8];
    __shared__ int bid_s;

    int b = blockIdx.x, t = threadIdx.x;
    int lane = t & 31, w = t >> 5;

    es[t]       = g_e[(size_t)b * NDIM + t];
    es[256 + t] = g_e[(size_t)b * NDIM + 256 + t];
    __syncthreads();

    int nc = g_ccnt[b];
    bool ovf = nc > CAP;
    int total = ovf ? NA : nc;

    unsigned long long best = 0xFFFFFFFFFFFFFFFFull;
    for (int ci = w; ci < total; ci += 8) {
        int code = ovf ? ci : g_cand[b * CAP + ci];
        const float* cr = cb + (size_t)code * NDIM;
        float d = 0.f;
        #pragma unroll
        for (int i = 0; i < 16; i++) d += es[lane + i * 32] * cr[lane + i * 32];
        #pragma unroll
        for (int o = 16; o; o >>= 1) d += __shfl_down_sync(0xFFFFFFFFu, d, o);
        if (lane == 0) {
            float s = g_cnorm[code] - 2.0f * d;
            unsigned long long k =
                ((unsigned long long)fkey(s) << 32) | (unsigned int)code;
            if (k < best) best = k;
        }
    }
    if (lane == 0) wkey[w] = best;
    __syncthreads();
    if (t == 0) {
        unsigned long long k = wkey[0];
        #pragma unroll
        for (int i = 1; i < 8; i++) if (wkey[i] < k) k = wkey[i];
        int bi = (int)(k & 0xFFFFFFFFull);
        if (bi < 0 || bi >= NA) bi = 0;
        out[b] = (float)bi;
        bid_s = bi;
    }
    __syncthreads();
    int bi = bid_s;
    out[NB + (size_t)b * NDIM + t]       = cb[(size_t)bi * NDIM + t];
    out[NB + (size_t)b * NDIM + 256 + t] = cb[(size_t)bi * NDIM + 256 + t];
}

// -------------------------------------------------------------------------------
extern "C" void kernel_launch(void* const* d_in, const int* in_sizes, int n_in,
                              void* d_out, int out_size) {
    const int*   zt = (const int*)d_in[0];
    const int*   zp = (const int*)d_in[1];
    const float* ew = (const float*)d_in[2];
    const float* w1 = (const float*)d_in[3];
    const float* b1 = (const float*)d_in[4];
    const float* w2 = (const float*)d_in[5];
    const float* b2 = (const float*)d_in[6];
    const float* cb = (const float*)d_in[7];
    float* out = (float*)d_out;

    __nv_bfloat16 *phA, *ph2A, *pw1s, *pw2s;
    cudaGetSymbolAddress((void**)&phA,  g_hA);
    cudaGetSymbolAddress((void**)&ph2A, g_h2A);
    cudaGetSymbolAddress((void**)&pw1s, g_w1s);
    cudaGetSymbolAddress((void**)&pw2s, g_w2s);

    cudaFuncSetAttribute(k_vq1, cudaFuncAttributeMaxDynamicSharedMemorySize, VQ_SMEM);
    cudaFuncSetAttribute((const void*)k_mlp<true , true >, cudaFuncAttributeMaxDynamicSharedMemorySize, MLP_SMEM);
    cudaFuncSetAttribute((const void*)k_mlp<false, false>, cudaFuncAttributeMaxDynamicSharedMemorySize, MLP_SMEM);

    k_prep   <<<NA + 1024 + (NB + 511) / 512, 512>>>(cb, w1, w2);
    k_embed  <<<NB, 512>>>(zt, zp, ew);
    k_mlp<true , true ><<<dim3(512 / 64, NB / 64), 128, MLP_SMEM>>>(phA,  pw1s, b1, ph2A, KH1);
    k_mlp<false, false><<<dim3(512 / 64, NB / 64), 128, MLP_SMEM>>>(ph2A, pw2s, b2, nullptr, KSPLIT);
    k_emargin<<<NB / 8, 256>>>();
    k_vq1    <<<dim3(NA / 128, NB / 128), 128, VQ_SMEM>>>();
    k_refine <<<NB, 256>>>(cb, out);
}